// round 1
// baseline (speedup 1.0000x reference)
#include <cuda_runtime.h>
#include <cstddef>

#define NMAX   100000
#define EMAX   3200000
#define DOUT   64
#define FIN    256

// Scratch (allocation-free rule: __device__ globals)
__device__ float g_xw [NMAX * DOUT];   // features @ W
__device__ float g_out[NMAX * DOUT];   // edge-aggregated output (no self loop)
__device__ float g_dinv[NMAX];
__device__ int   g_deg [NMAX];

// ---------------------------------------------------------------------------
// helpers
// ---------------------------------------------------------------------------
__device__ __forceinline__ void ffma2(float2& acc, float2 a, float2 b) {
    unsigned long long& c = reinterpret_cast<unsigned long long&>(acc);
    const unsigned long long& ua = reinterpret_cast<const unsigned long long&>(a);
    const unsigned long long& ub = reinterpret_cast<const unsigned long long&>(b);
    asm("fma.rn.f32x2 %0, %1, %2, %0;" : "+l"(c) : "l"(ua), "l"(ub));
}

__device__ __forceinline__ void red_add_v4(float* addr, float4 v) {
    asm volatile("red.global.add.v4.f32 [%0], {%1,%2,%3,%4};"
                 :: "l"(addr), "f"(v.x), "f"(v.y), "f"(v.z), "f"(v.w)
                 : "memory");
}

// ---------------------------------------------------------------------------
// 1) init: zero g_out, deg = 1 (self loop)
// ---------------------------------------------------------------------------
__global__ void init_kernel(int n) {
    int i = blockIdx.x * blockDim.x + threadIdx.x;
    int total4 = n * (DOUT / 4);
    if (i < total4) reinterpret_cast<float4*>(g_out)[i] = make_float4(0.f, 0.f, 0.f, 0.f);
    if (i < n) g_deg[i] = 1;
}

// ---------------------------------------------------------------------------
// 2) in-degree of dst
// ---------------------------------------------------------------------------
__global__ void degree_kernel(const int* __restrict__ dst, int e) {
    int i = blockIdx.x * blockDim.x + threadIdx.x;
    int i4 = i * 4;
    if (i4 + 3 < e) {
        int4 d = *reinterpret_cast<const int4*>(dst + i4);
        atomicAdd(&g_deg[d.x], 1);
        atomicAdd(&g_deg[d.y], 1);
        atomicAdd(&g_deg[d.z], 1);
        atomicAdd(&g_deg[d.w], 1);
    } else if (i4 < e) {
        for (int j = i4; j < e; j++) atomicAdd(&g_deg[dst[j]], 1);
    }
}

// ---------------------------------------------------------------------------
// 3) dinv = rsqrt(deg)   (deg >= 1 always due to self loop)
// ---------------------------------------------------------------------------
__global__ void dinv_kernel(int n) {
    int i = blockIdx.x * blockDim.x + threadIdx.x;
    if (i < n) g_dinv[i] = rsqrtf((float)g_deg[i]);
}

// ---------------------------------------------------------------------------
// 4) GEMM:  g_xw[M,64] = A[M,256] @ B[256,64]    (fp32, f32x2 packed FMA)
//    Block tile 128x64, K-chunk 16, thread tile 8x4, 256 threads.
// ---------------------------------------------------------------------------
__global__ void __launch_bounds__(256) gemm_kernel(const float* __restrict__ A,
                                                   const float* __restrict__ B,
                                                   int M) {
    __shared__ float As[16][128];
    __shared__ float Bs[16][64];

    const int tid = threadIdx.x;
    const int tx  = tid & 15;          // output dim group: dims [tx*4, tx*4+4)
    const int ty  = tid >> 4;          // node group:       nodes [ty*8, ty*8+8)
    const int bm  = blockIdx.x * 128;

    // A-tile loading: thread -> (node = tid/2, k-half = (tid&1)*8), 2 x float4
    const int  a_node  = bm + (tid >> 1);
    const int  a_k     = (tid & 1) * 8;
    const bool a_valid = a_node < M;
    const float* Ap    = A + (size_t)a_node * FIN + a_k;

    // B-tile loading: thread -> (k = tid/16, d = (tid&15)*4), 1 x float4
    const int b_k = tid >> 4;
    const int b_d = (tid & 15) * 4;

    float2 acc[8][2];
#pragma unroll
    for (int m = 0; m < 8; m++) {
        acc[m][0] = make_float2(0.f, 0.f);
        acc[m][1] = make_float2(0.f, 0.f);
    }

    for (int k0 = 0; k0 < FIN; k0 += 16) {
        float4 a0 = make_float4(0.f, 0.f, 0.f, 0.f), a1 = a0;
        if (a_valid) {
            a0 = *reinterpret_cast<const float4*>(Ap + k0);
            a1 = *reinterpret_cast<const float4*>(Ap + k0 + 4);
        }
        float4 bb = *reinterpret_cast<const float4*>(B + (k0 + b_k) * DOUT + b_d);

        __syncthreads();
        const int an = tid >> 1;
        As[a_k + 0][an] = a0.x; As[a_k + 1][an] = a0.y;
        As[a_k + 2][an] = a0.z; As[a_k + 3][an] = a0.w;
        As[a_k + 4][an] = a1.x; As[a_k + 5][an] = a1.y;
        As[a_k + 6][an] = a1.z; As[a_k + 7][an] = a1.w;
        *reinterpret_cast<float4*>(&Bs[b_k][b_d]) = bb;
        __syncthreads();

#pragma unroll
        for (int kk = 0; kk < 16; kk++) {
            float4 af0 = *reinterpret_cast<const float4*>(&As[kk][ty * 8]);
            float4 af1 = *reinterpret_cast<const float4*>(&As[kk][ty * 8 + 4]);
            float4 bf  = *reinterpret_cast<const float4*>(&Bs[kk][tx * 4]);
            float  a[8] = {af0.x, af0.y, af0.z, af0.w, af1.x, af1.y, af1.z, af1.w};
            float2 b0 = make_float2(bf.x, bf.y);
            float2 b1 = make_float2(bf.z, bf.w);
#pragma unroll
            for (int m = 0; m < 8; m++) {
                float2 am = make_float2(a[m], a[m]);
                ffma2(acc[m][0], am, b0);
                ffma2(acc[m][1], am, b1);
            }
        }
    }

#pragma unroll
    for (int m = 0; m < 8; m++) {
        int node = bm + ty * 8 + m;
        if (node < M) {
            float4 r = make_float4(acc[m][0].x, acc[m][0].y, acc[m][1].x, acc[m][1].y);
            *reinterpret_cast<float4*>(g_xw + (size_t)node * DOUT + tx * 4) = r;
        }
    }
}

// ---------------------------------------------------------------------------
// 5) scatter:  out[dst] += xw[src] * dinv[src]*dinv[dst]
//    16 threads per edge, float4 lanes, red.global.add.v4.f32
// ---------------------------------------------------------------------------
__global__ void scatter_kernel(const int* __restrict__ src,
                               const int* __restrict__ dst, int e) {
    int idx = blockIdx.x * blockDim.x + threadIdx.x;
    int eid = idx >> 4;
    int q   = idx & 15;
    if (eid >= e) return;
    int s = src[eid];
    int d = dst[eid];
    float norm = g_dinv[s] * g_dinv[d];
    float4 v = *reinterpret_cast<const float4*>(g_xw + ((size_t)s << 6) + (q << 2));
    float4 r = make_float4(v.x * norm, v.y * norm, v.z * norm, v.w * norm);
    red_add_v4(g_out + ((size_t)d << 6) + (q << 2), r);
}

// ---------------------------------------------------------------------------
// 6) gather:  out[i] = g_out[x[i]] + xw[x[i]]*dinv^2 (self loop) + b
// ---------------------------------------------------------------------------
__global__ void gather_kernel(const int* __restrict__ x,
                              const float* __restrict__ b,
                              float* __restrict__ out, int nidx) {
    int idx = blockIdx.x * blockDim.x + threadIdx.x;
    int i = idx >> 4;
    int q = idx & 15;
    if (i >= nidx) return;
    int n = x[i];
    float dn = g_dinv[n];
    float sl = dn * dn;
    size_t off = ((size_t)n << 6) + (q << 2);
    float4 o  = *reinterpret_cast<const float4*>(g_out + off);
    float4 w  = *reinterpret_cast<const float4*>(g_xw + off);
    float4 bb = *reinterpret_cast<const float4*>(b + (q << 2));
    float4 r = make_float4(o.x + w.x * sl + bb.x,
                           o.y + w.y * sl + bb.y,
                           o.z + w.z * sl + bb.z,
                           o.w + w.w * sl + bb.w);
    *reinterpret_cast<float4*>(out + ((size_t)i << 6) + (q << 2)) = r;
}

// ---------------------------------------------------------------------------
extern "C" void kernel_launch(void* const* d_in, const int* in_sizes, int n_in,
                              void* d_out, int out_size) {
    const float* features   = (const float*)d_in[0];
    const int*   edge_index = (const int*)  d_in[1];
    const float* W          = (const float*)d_in[2];
    const float* b          = (const float*)d_in[3];
    const int*   x          = (const int*)  d_in[4];
    float*       out        = (float*)d_out;

    const int N  = in_sizes[0] / FIN;
    const int E  = in_sizes[1] / 2;
    const int NX = in_sizes[4];

    const int* src = edge_index;
    const int* dst = edge_index + E;

    init_kernel<<<(N * (DOUT / 4) + 255) / 256, 256>>>(N);
    degree_kernel<<<((E + 3) / 4 + 255) / 256, 256>>>(dst, E);
    dinv_kernel<<<(N + 255) / 256, 256>>>(N);
    gemm_kernel<<<(N + 127) / 128, 256>>>(features, W, N);

    long long scatter_work = (long long)E * 16;
    scatter_kernel<<<(int)((scatter_work + 255) / 256), 256>>>(src, dst, E);

    gather_kernel<<<(NX * 16 + 255) / 256, 256>>>(x, b, out, NX);
}

// round 2
// speedup vs baseline: 1.3146x; 1.3146x over previous
#include <cuda_runtime.h>
#include <cstddef>

#define NMAX   100000
#define EMAX   3200000
#define DOUT   64
#define FIN    256
#define NBMAX  128            // ceil(NMAX/1024) = 98

// Scratch (__device__ globals: allocation-free rule)
__device__ float g_xw [NMAX * DOUT];   // features @ W
__device__ float g_out[NMAX * DOUT];   // aggregated output (+ self loop + bias)
__device__ float g_dinv[NMAX];
__device__ int   g_ecnt[NMAX];         // in-degree from edges (no self loop)
__device__ int   g_off [NMAX];         // CSR offsets (exclusive scan of ecnt)
__device__ int   g_cur [NMAX];         // fill cursors
__device__ int   g_csr [EMAX];         // src indices grouped by dst
__device__ int   g_bsum[NBMAX];
__device__ int   g_bscan[NBMAX];

// ---------------------------------------------------------------------------
__device__ __forceinline__ void ffma2(float2& acc, float2 a, float2 b) {
    unsigned long long& c = reinterpret_cast<unsigned long long&>(acc);
    const unsigned long long& ua = reinterpret_cast<const unsigned long long&>(a);
    const unsigned long long& ub = reinterpret_cast<const unsigned long long&>(b);
    asm("fma.rn.f32x2 %0, %1, %2, %0;" : "+l"(c) : "l"(ua), "l"(ub));
}

// ---------------------------------------------------------------------------
// 1) zero edge counts
// ---------------------------------------------------------------------------
__global__ void init_kernel(int n) {
    int i = blockIdx.x * blockDim.x + threadIdx.x;
    if (i < n) g_ecnt[i] = 0;
}

// ---------------------------------------------------------------------------
// 2) in-degree of dst (edges only)
// ---------------------------------------------------------------------------
__global__ void degree_kernel(const int* __restrict__ dst, int e) {
    int i = blockIdx.x * blockDim.x + threadIdx.x;
    int i4 = i * 4;
    if (i4 + 3 < e) {
        int4 d = *reinterpret_cast<const int4*>(dst + i4);
        atomicAdd(&g_ecnt[d.x], 1);
        atomicAdd(&g_ecnt[d.y], 1);
        atomicAdd(&g_ecnt[d.z], 1);
        atomicAdd(&g_ecnt[d.w], 1);
    } else if (i4 < e) {
        for (int j = i4; j < e; j++) atomicAdd(&g_ecnt[dst[j]], 1);
    }
}

// ---------------------------------------------------------------------------
// 3) dinv = rsqrt(deg + 1)  (self loop)
// ---------------------------------------------------------------------------
__global__ void dinv_kernel(int n) {
    int i = blockIdx.x * blockDim.x + threadIdx.x;
    if (i < n) g_dinv[i] = rsqrtf((float)(g_ecnt[i] + 1));
}

// ---------------------------------------------------------------------------
// 4) exclusive scan of g_ecnt -> g_off  (3 kernels, 1024 elems/block)
// ---------------------------------------------------------------------------
__global__ void scan1_kernel(int n) {
    __shared__ int warp_sums[8];
    int blk = blockIdx.x, tid = threadIdx.x;
    int base = blk * 1024 + tid * 4;
    int v[4];
#pragma unroll
    for (int j = 0; j < 4; j++) v[j] = (base + j < n) ? g_ecnt[base + j] : 0;
    int tsum = v[0] + v[1] + v[2] + v[3];
    int lane = tid & 31, wid = tid >> 5;
    int x = tsum;
#pragma unroll
    for (int o = 1; o < 32; o <<= 1) {
        int y = __shfl_up_sync(~0u, x, o);
        if (lane >= o) x += y;
    }
    if (lane == 31) warp_sums[wid] = x;
    __syncthreads();
    if (wid == 0) {
        int w = (lane < 8) ? warp_sums[lane] : 0;
#pragma unroll
        for (int o = 1; o < 8; o <<= 1) {
            int y = __shfl_up_sync(~0u, w, o);
            if (lane >= o) w += y;
        }
        if (lane < 8) warp_sums[lane] = w;
    }
    __syncthreads();
    int excl = x - tsum + (wid > 0 ? warp_sums[wid - 1] : 0);
    int run = excl;
#pragma unroll
    for (int j = 0; j < 4; j++) {
        if (base + j < n) g_off[base + j] = run;
        run += v[j];
    }
    if (tid == 0) g_bsum[blk] = warp_sums[7];
}

__global__ void scan2_kernel(int nb) {
    __shared__ int ws[4];
    int tid = threadIdx.x, lane = tid & 31, wid = tid >> 5;
    int v = (tid < nb) ? g_bsum[tid] : 0;
    int x = v;
#pragma unroll
    for (int o = 1; o < 32; o <<= 1) {
        int y = __shfl_up_sync(~0u, x, o);
        if (lane >= o) x += y;
    }
    if (lane == 31) ws[wid] = x;
    __syncthreads();
    if (tid == 0) {
        int s = 0;
        for (int i = 0; i < 4; i++) { int t = ws[i]; ws[i] = s; s += t; }
    }
    __syncthreads();
    if (tid < NBMAX) g_bscan[tid] = x - v + ws[wid];
}

__global__ void scan3_kernel(int n) {
    int i = blockIdx.x * blockDim.x + threadIdx.x;
    if (i < n) {
        int o = g_off[i] + g_bscan[i >> 10];
        g_off[i] = o;
        g_cur[i] = o;
    }
}

// ---------------------------------------------------------------------------
// 5) fill CSR: src indices grouped by dst
// ---------------------------------------------------------------------------
__global__ void fill_kernel(const int* __restrict__ src,
                            const int* __restrict__ dst, int e) {
    int i = blockIdx.x * blockDim.x + threadIdx.x;
    if (i < e) {
        int d = dst[i];
        int pos = atomicAdd(&g_cur[d], 1);
        g_csr[pos] = src[i];
    }
}

// ---------------------------------------------------------------------------
// 6) GEMM:  g_xw[M,64] = A[M,256] @ B[256,64]  (fp32, f32x2)
// ---------------------------------------------------------------------------
__global__ void __launch_bounds__(256, 4) gemm_kernel(const float* __restrict__ A,
                                                      const float* __restrict__ B,
                                                      int M) {
    __shared__ float As[16][128];
    __shared__ float Bs[16][64];

    const int tid = threadIdx.x;
    const int tx  = tid & 15;
    const int ty  = tid >> 4;
    const int bm  = blockIdx.x * 128;

    const int  a_node  = bm + (tid >> 1);
    const int  a_k     = (tid & 1) * 8;
    const bool a_valid = a_node < M;
    const float* Ap    = A + (size_t)a_node * FIN + a_k;

    const int b_k = tid >> 4;
    const int b_d = (tid & 15) * 4;

    float2 acc[8][2];
#pragma unroll
    for (int m = 0; m < 8; m++) {
        acc[m][0] = make_float2(0.f, 0.f);
        acc[m][1] = make_float2(0.f, 0.f);
    }

    for (int k0 = 0; k0 < FIN; k0 += 16) {
        float4 a0 = make_float4(0.f, 0.f, 0.f, 0.f), a1 = a0;
        if (a_valid) {
            a0 = *reinterpret_cast<const float4*>(Ap + k0);
            a1 = *reinterpret_cast<const float4*>(Ap + k0 + 4);
        }
        float4 bb = *reinterpret_cast<const float4*>(B + (k0 + b_k) * DOUT + b_d);

        __syncthreads();
        const int an = tid >> 1;
        As[a_k + 0][an] = a0.x; As[a_k + 1][an] = a0.y;
        As[a_k + 2][an] = a0.z; As[a_k + 3][an] = a0.w;
        As[a_k + 4][an] = a1.x; As[a_k + 5][an] = a1.y;
        As[a_k + 6][an] = a1.z; As[a_k + 7][an] = a1.w;
        *reinterpret_cast<float4*>(&Bs[b_k][b_d]) = bb;
        __syncthreads();

#pragma unroll
        for (int kk = 0; kk < 16; kk++) {
            float4 af0 = *reinterpret_cast<const float4*>(&As[kk][ty * 8]);
            float4 af1 = *reinterpret_cast<const float4*>(&As[kk][ty * 8 + 4]);
            float4 bf  = *reinterpret_cast<const float4*>(&Bs[kk][tx * 4]);
            float  a[8] = {af0.x, af0.y, af0.z, af0.w, af1.x, af1.y, af1.z, af1.w};
            float2 b0 = make_float2(bf.x, bf.y);
            float2 b1 = make_float2(bf.z, bf.w);
#pragma unroll
            for (int m = 0; m < 8; m++) {
                float2 am = make_float2(a[m], a[m]);
                ffma2(acc[m][0], am, b0);
                ffma2(acc[m][1], am, b1);
            }
        }
    }

#pragma unroll
    for (int m = 0; m < 8; m++) {
        int node = bm + ty * 8 + m;
        if (node < M) {
            float4 r = make_float4(acc[m][0].x, acc[m][0].y, acc[m][1].x, acc[m][1].y);
            *reinterpret_cast<float4*>(g_xw + (size_t)node * DOUT + tx * 4) = r;
        }
    }
}

// ---------------------------------------------------------------------------
// 7) aggregate: one warp per node.  out[n] = sum_in xw[s]*dinv[s]*dinv[n]
//               + xw[n]*dinv[n]^2 + b
// ---------------------------------------------------------------------------
__global__ void __launch_bounds__(256) aggregate_kernel(const float* __restrict__ b,
                                                        int n) {
    int node = (blockIdx.x * blockDim.x + threadIdx.x) >> 5;
    int lane = threadIdx.x & 31;
    if (node >= n) return;

    float dn    = g_dinv[node];
    int   start = g_off[node];
    int   end   = start + g_ecnt[node];

    float2 w = *reinterpret_cast<const float2*>(g_xw + ((size_t)node << 6) + (lane << 1));
    float  sl = dn * dn;
    float2 acc = make_float2(w.x * sl, w.y * sl);

    int j = start;
    for (; j + 1 < end; j += 2) {
        int s0 = g_csr[j];
        int s1 = g_csr[j + 1];
        float nm0 = g_dinv[s0] * dn;
        float nm1 = g_dinv[s1] * dn;
        float2 v0 = *reinterpret_cast<const float2*>(g_xw + ((size_t)s0 << 6) + (lane << 1));
        float2 v1 = *reinterpret_cast<const float2*>(g_xw + ((size_t)s1 << 6) + (lane << 1));
        acc.x += v0.x * nm0; acc.y += v0.y * nm0;
        acc.x += v1.x * nm1; acc.y += v1.y * nm1;
    }
    if (j < end) {
        int s = g_csr[j];
        float nm = g_dinv[s] * dn;
        float2 v = *reinterpret_cast<const float2*>(g_xw + ((size_t)s << 6) + (lane << 1));
        acc.x += v.x * nm; acc.y += v.y * nm;
    }

    float2 bb = *reinterpret_cast<const float2*>(b + (lane << 1));
    acc.x += bb.x; acc.y += bb.y;
    *reinterpret_cast<float2*>(g_out + ((size_t)node << 6) + (lane << 1)) = acc;
}

// ---------------------------------------------------------------------------
// 8) final gather: out[i] = g_out[x[i]]
// ---------------------------------------------------------------------------
__global__ void gather_kernel(const int* __restrict__ x,
                              float* __restrict__ out, int nidx) {
    int idx = blockIdx.x * blockDim.x + threadIdx.x;
    int i = idx >> 4;
    int q = idx & 15;
    if (i >= nidx) return;
    int nd = x[i];
    float4 v = *reinterpret_cast<const float4*>(g_out + ((size_t)nd << 6) + (q << 2));
    *reinterpret_cast<float4*>(out + ((size_t)i << 6) + (q << 2)) = v;
}

// ---------------------------------------------------------------------------
extern "C" void kernel_launch(void* const* d_in, const int* in_sizes, int n_in,
                              void* d_out, int out_size) {
    const float* features   = (const float*)d_in[0];
    const int*   edge_index = (const int*)  d_in[1];
    const float* W          = (const float*)d_in[2];
    const float* b          = (const float*)d_in[3];
    const int*   x          = (const int*)  d_in[4];
    float*       out        = (float*)d_out;

    const int N  = in_sizes[0] / FIN;
    const int E  = in_sizes[1] / 2;
    const int NX = in_sizes[4];

    const int* src = edge_index;
    const int* dst = edge_index + E;

    const int NB = (N + 1023) / 1024;

    init_kernel<<<(N + 255) / 256, 256>>>(N);
    degree_kernel<<<((E + 3) / 4 + 255) / 256, 256>>>(dst, E);
    gemm_kernel<<<(N + 127) / 128, 256>>>(features, W, N);
    dinv_kernel<<<(N + 255) / 256, 256>>>(N);
    scan1_kernel<<<NB, 256>>>(N);
    scan2_kernel<<<1, 128>>>(NB);
    scan3_kernel<<<(N + 255) / 256, 256>>>(N);
    fill_kernel<<<(E + 255) / 256, 256>>>(src, dst, E);

    long long agg_threads = (long long)N * 32;
    aggregate_kernel<<<(int)((agg_threads + 255) / 256), 256>>>(b, N);

    gather_kernel<<<(NX * 16 + 255) / 256, 256>>>(x, out, NX);
}

// round 3
// speedup vs baseline: 1.5722x; 1.1959x over previous
#include <cuda_runtime.h>
#include <cuda_bf16.h>
#include <cstddef>

#define NMAX   100000
#define EMAX   3200000
#define DOUT   64
#define FIN    256
#define NBMAX  128

// Scratch (__device__ globals: allocation-free rule)
__device__ float g_xw [NMAX * DOUT];
__device__ float g_out[NMAX * DOUT];
__device__ float g_dinv[NMAX];
__device__ int   g_ecnt[NMAX];
__device__ int   g_off [NMAX];
__device__ int   g_cur [NMAX];
__device__ int   g_csr [EMAX];
__device__ int   g_bsum[NBMAX];
__device__ int   g_bscan[NBMAX];
__device__ __nv_bfloat16 g_wth[DOUT * FIN];   // W^T hi  [64][256]
__device__ __nv_bfloat16 g_wtl[DOUT * FIN];   // W^T lo

// ---------------------------------------------------------------------------
__device__ __forceinline__ unsigned pack_bf2(float x, float y) {
    __nv_bfloat162 t = __floats2bfloat162_rn(x, y);
    return *reinterpret_cast<unsigned*>(&t);
}

__device__ __forceinline__ void ldsm4(unsigned* r, unsigned addr) {
    asm volatile("ldmatrix.sync.aligned.m8n8.x4.shared.b16 {%0,%1,%2,%3}, [%4];\n"
                 : "=r"(r[0]), "=r"(r[1]), "=r"(r[2]), "=r"(r[3]) : "r"(addr));
}

__device__ __forceinline__ void mma_bf16(float* c, const unsigned* a,
                                         unsigned b0, unsigned b1) {
    asm volatile("mma.sync.aligned.m16n8k16.row.col.f32.bf16.bf16.f32 "
                 "{%0,%1,%2,%3}, {%4,%5,%6,%7}, {%8,%9}, {%0,%1,%2,%3};\n"
                 : "+f"(c[0]), "+f"(c[1]), "+f"(c[2]), "+f"(c[3])
                 : "r"(a[0]), "r"(a[1]), "r"(a[2]), "r"(a[3]), "r"(b0), "r"(b1));
}

// ---------------------------------------------------------------------------
// 1) zero edge counts
// ---------------------------------------------------------------------------
__global__ void init_kernel(int n) {
    int i = blockIdx.x * blockDim.x + threadIdx.x;
    if (i < n) g_ecnt[i] = 0;
}

// ---------------------------------------------------------------------------
// 2) in-degree of dst
// ---------------------------------------------------------------------------
__global__ void degree_kernel(const int* __restrict__ dst, int e) {
    int i = blockIdx.x * blockDim.x + threadIdx.x;
    int i4 = i * 4;
    if (i4 + 3 < e) {
        int4 d = *reinterpret_cast<const int4*>(dst + i4);
        atomicAdd(&g_ecnt[d.x], 1);
        atomicAdd(&g_ecnt[d.y], 1);
        atomicAdd(&g_ecnt[d.z], 1);
        atomicAdd(&g_ecnt[d.w], 1);
    } else if (i4 < e) {
        for (int j = i4; j < e; j++) atomicAdd(&g_ecnt[dst[j]], 1);
    }
}

// ---------------------------------------------------------------------------
// 3) split W into hi/lo bf16, transposed to [n][k]
// ---------------------------------------------------------------------------
__global__ void wsplit_kernel(const float* __restrict__ W) {
    int idx = blockIdx.x * blockDim.x + threadIdx.x;
    if (idx < FIN * DOUT) {
        int k = idx >> 6, n = idx & 63;
        float a = W[idx];
        __nv_bfloat16 h = __float2bfloat16(a);
        float r = a - __bfloat162float(h);
        g_wth[n * FIN + k] = h;
        g_wtl[n * FIN + k] = __float2bfloat16(r);
    }
}

// ---------------------------------------------------------------------------
// 4) GEMM via split-bf16 HMMA:  g_xw[M,64] = A[M,256] @ W[256,64]
//    block: 128 rows x 64 cols, 8 warps; warp = 16 rows x 64 cols
// ---------------------------------------------------------------------------
__global__ void __launch_bounds__(256) gemm_kernel(const float* __restrict__ A, int M) {
    __shared__ __align__(16) __nv_bfloat16 Ah[128 * 24];  // 16 k, pad to 24
    __shared__ __align__(16) __nv_bfloat16 Al[128 * 24];
    __shared__ __align__(16) __nv_bfloat16 Wh[64 * 72];   // 64 k chunk, pad 72
    __shared__ __align__(16) __nv_bfloat16 Wl[64 * 72];

    const int tid  = threadIdx.x;
    const int lane = tid & 31;
    const int wid  = tid >> 5;
    const int bm   = blockIdx.x * 128;

    float acc[8][4];
#pragma unroll
    for (int t = 0; t < 8; t++)
#pragma unroll
        for (int j = 0; j < 4; j++) acc[t][j] = 0.f;

    // A tile load mapping: row = tid/2, col-half = (tid&1)*8
    const int  a_row   = tid >> 1;
    const int  a_col   = (tid & 1) * 8;
    const bool a_valid = (bm + a_row) < M;
    const float* Ap    = A + (size_t)(bm + a_row) * FIN + a_col;

    // ldmatrix addresses
    const unsigned ah_base = (unsigned)__cvta_generic_to_shared(Ah);
    const unsigned al_base = (unsigned)__cvta_generic_to_shared(Al);
    const unsigned wh_base = (unsigned)__cvta_generic_to_shared(Wh);
    const unsigned wl_base = (unsigned)__cvta_generic_to_shared(Wl);

    const unsigned a_frag_off =
        (unsigned)(((wid * 16 + (lane & 15)) * 24 + (lane >> 4) * 8) * 2);
    const int n_off = (lane & 7) + ((lane >> 4) & 1) * 8;
    const int k_off = ((lane >> 3) & 1) * 8;

    for (int kc = 0; kc < 4; kc++) {
        __syncthreads();   // previous chunk's MMAs done before W overwrite
        // stage W chunk [64 n][64 k] hi+lo from global (pre-split)
        for (int u = tid; u < 512; u += 256) {
            int n = u >> 3, kg = u & 7;
            const uint4* sh = reinterpret_cast<const uint4*>(g_wth + n * FIN + kc * 64 + kg * 8);
            const uint4* sl = reinterpret_cast<const uint4*>(g_wtl + n * FIN + kc * 64 + kg * 8);
            *reinterpret_cast<uint4*>(Wh + n * 72 + kg * 8) = *sh;
            *reinterpret_cast<uint4*>(Wl + n * 72 + kg * 8) = *sl;
        }

        for (int ks4 = 0; ks4 < 4; ks4++) {
            float4 a0 = make_float4(0.f, 0.f, 0.f, 0.f), a1 = a0;
            if (a_valid) {
                const float* p = Ap + kc * 64 + ks4 * 16;
                a0 = *reinterpret_cast<const float4*>(p);
                a1 = *reinterpret_cast<const float4*>(p + 4);
            }
            float v[8] = {a0.x, a0.y, a0.z, a0.w, a1.x, a1.y, a1.z, a1.w};
            unsigned hh[4], ll[4];
#pragma unroll
            for (int j = 0; j < 4; j++) {
                float x = v[2 * j], y = v[2 * j + 1];
                __nv_bfloat16 hx = __float2bfloat16(x);
                __nv_bfloat16 hy = __float2bfloat16(y);
                float rx = x - __bfloat162float(hx);
                float ry = y - __bfloat162float(hy);
                __nv_bfloat162 hp; hp.x = hx; hp.y = hy;
                hh[j] = *reinterpret_cast<unsigned*>(&hp);
                ll[j] = pack_bf2(rx, ry);
            }
            __syncthreads();   // previous k-step's MMAs done (also W visible)
            *reinterpret_cast<uint4*>(Ah + a_row * 24 + a_col) =
                make_uint4(hh[0], hh[1], hh[2], hh[3]);
            *reinterpret_cast<uint4*>(Al + a_row * 24 + a_col) =
                make_uint4(ll[0], ll[1], ll[2], ll[3]);
            __syncthreads();

            unsigned afh[4], afl[4];
            ldsm4(afh, ah_base + a_frag_off);
            ldsm4(afl, al_base + a_frag_off);
#pragma unroll
            for (int p = 0; p < 4; p++) {
                unsigned boff = (unsigned)(((p * 16 + n_off) * 72 + ks4 * 16 + k_off) * 2);
                unsigned bh[4], bl[4];
                ldsm4(bh, wh_base + boff);
                ldsm4(bl, wl_base + boff);
                mma_bf16(acc[2 * p],     afh, bh[0], bh[1]);
                mma_bf16(acc[2 * p],     afl, bh[0], bh[1]);
                mma_bf16(acc[2 * p],     afh, bl[0], bl[1]);
                mma_bf16(acc[2 * p + 1], afh, bh[2], bh[3]);
                mma_bf16(acc[2 * p + 1], afl, bh[2], bh[3]);
                mma_bf16(acc[2 * p + 1], afh, bl[2], bl[3]);
            }
        }
    }

    // epilogue: c0,c1 -> row r0, c2,c3 -> row r0+8
    int r0 = bm + wid * 16 + (lane >> 2);
    int c0 = (lane & 3) * 2;
#pragma unroll
    for (int nt = 0; nt < 8; nt++) {
        if (r0 < M) {
            float2 w0 = make_float2(acc[nt][0], acc[nt][1]);
            *reinterpret_cast<float2*>(g_xw + (size_t)r0 * DOUT + nt * 8 + c0) = w0;
        }
        if (r0 + 8 < M) {
            float2 w1 = make_float2(acc[nt][2], acc[nt][3]);
            *reinterpret_cast<float2*>(g_xw + (size_t)(r0 + 8) * DOUT + nt * 8 + c0) = w1;
        }
    }
}

// ---------------------------------------------------------------------------
// 5) scan pass 1 (+ dinv fused)
// ---------------------------------------------------------------------------
__global__ void scan1_kernel(int n) {
    __shared__ int warp_sums[8];
    int blk = blockIdx.x, tid = threadIdx.x;
    int base = blk * 1024 + tid * 4;
    int v[4];
#pragma unroll
    for (int j = 0; j < 4; j++) v[j] = (base + j < n) ? g_ecnt[base + j] : 0;
#pragma unroll
    for (int j = 0; j < 4; j++)
        if (base + j < n) g_dinv[base + j] = rsqrtf((float)(v[j] + 1));
    int tsum = v[0] + v[1] + v[2] + v[3];
    int lane = tid & 31, wid = tid >> 5;
    int x = tsum;
#pragma unroll
    for (int o = 1; o < 32; o <<= 1) {
        int y = __shfl_up_sync(~0u, x, o);
        if (lane >= o) x += y;
    }
    if (lane == 31) warp_sums[wid] = x;
    __syncthreads();
    if (wid == 0) {
        int w = (lane < 8) ? warp_sums[lane] : 0;
#pragma unroll
        for (int o = 1; o < 8; o <<= 1) {
            int y = __shfl_up_sync(~0u, w, o);
            if (lane >= o) w += y;
        }
        if (lane < 8) warp_sums[lane] = w;
    }
    __syncthreads();
    int excl = x - tsum + (wid > 0 ? warp_sums[wid - 1] : 0);
    int run = excl;
#pragma unroll
    for (int j = 0; j < 4; j++) {
        if (base + j < n) g_off[base + j] = run;
        run += v[j];
    }
    if (tid == 0) g_bsum[blk] = warp_sums[7];
}

__global__ void scan2_kernel(int nb) {
    __shared__ int ws[4];
    int tid = threadIdx.x, lane = tid & 31, wid = tid >> 5;
    int v = (tid < nb) ? g_bsum[tid] : 0;
    int x = v;
#pragma unroll
    for (int o = 1; o < 32; o <<= 1) {
        int y = __shfl_up_sync(~0u, x, o);
        if (lane >= o) x += y;
    }
    if (lane == 31) ws[wid] = x;
    __syncthreads();
    if (tid == 0) {
        int s = 0;
        for (int i = 0; i < 4; i++) { int t = ws[i]; ws[i] = s; s += t; }
    }
    __syncthreads();
    if (tid < NBMAX) g_bscan[tid] = x - v + ws[wid];
}

__global__ void scan3_kernel(int n) {
    int i = blockIdx.x * blockDim.x + threadIdx.x;
    if (i < n) {
        int o = g_off[i] + g_bscan[i >> 10];
        g_off[i] = o;
        g_cur[i] = o;
    }
}

// ---------------------------------------------------------------------------
// 6) fill CSR
// ---------------------------------------------------------------------------
__global__ void fill_kernel(const int* __restrict__ src,
                            const int* __restrict__ dst, int e) {
    int i = blockIdx.x * blockDim.x + threadIdx.x;
    if (i < e) {
        int d = dst[i];
        int pos = atomicAdd(&g_cur[d], 1);
        g_csr[pos] = src[i];
    }
}

// ---------------------------------------------------------------------------
// 7) aggregate: one warp per node
// ---------------------------------------------------------------------------
__global__ void __launch_bounds__(256) aggregate_kernel(const float* __restrict__ b,
                                                        int n) {
    int node = (blockIdx.x * blockDim.x + threadIdx.x) >> 5;
    int lane = threadIdx.x & 31;
    if (node >= n) return;

    float dn    = g_dinv[node];
    int   start = g_off[node];
    int   end   = start + g_ecnt[node];

    float2 w = *reinterpret_cast<const float2*>(g_xw + ((size_t)node << 6) + (lane << 1));
    float  sl = dn * dn;
    float2 acc = make_float2(w.x * sl, w.y * sl);

    int j = start;
    for (; j + 1 < end; j += 2) {
        int s0 = g_csr[j];
        int s1 = g_csr[j + 1];
        float nm0 = g_dinv[s0] * dn;
        float nm1 = g_dinv[s1] * dn;
        float2 v0 = *reinterpret_cast<const float2*>(g_xw + ((size_t)s0 << 6) + (lane << 1));
        float2 v1 = *reinterpret_cast<const float2*>(g_xw + ((size_t)s1 << 6) + (lane << 1));
        acc.x += v0.x * nm0; acc.y += v0.y * nm0;
        acc.x += v1.x * nm1; acc.y += v1.y * nm1;
    }
    if (j < end) {
        int s = g_csr[j];
        float nm = g_dinv[s] * dn;
        float2 v = *reinterpret_cast<const float2*>(g_xw + ((size_t)s << 6) + (lane << 1));
        acc.x += v.x * nm; acc.y += v.y * nm;
    }

    float2 bb = *reinterpret_cast<const float2*>(b + (lane << 1));
    acc.x += bb.x; acc.y += bb.y;
    *reinterpret_cast<float2*>(g_out + ((size_t)node << 6) + (lane << 1)) = acc;
}

// ---------------------------------------------------------------------------
// 8) final gather
// ---------------------------------------------------------------------------
__global__ void gather_kernel(const int* __restrict__ x,
                              float* __restrict__ out, int nidx) {
    int idx = blockIdx.x * blockDim.x + threadIdx.x;
    int i = idx >> 4;
    int q = idx & 15;
    if (i >= nidx) return;
    int nd = x[i];
    float4 v = *reinterpret_cast<const float4*>(g_out + ((size_t)nd << 6) + (q << 2));
    *reinterpret_cast<float4*>(out + ((size_t)i << 6) + (q << 2)) = v;
}

// ---------------------------------------------------------------------------
extern "C" void kernel_launch(void* const* d_in, const int* in_sizes, int n_in,
                              void* d_out, int out_size) {
    const float* features   = (const float*)d_in[0];
    const int*   edge_index = (const int*)  d_in[1];
    const float* W          = (const float*)d_in[2];
    const float* b          = (const float*)d_in[3];
    const int*   x          = (const int*)  d_in[4];
    float*       out        = (float*)d_out;

    const int N  = in_sizes[0] / FIN;
    const int E  = in_sizes[1] / 2;
    const int NX = in_sizes[4];

    const int* src = edge_index;
    const int* dst = edge_index + E;
    const int NB = (N + 1023) / 1024;

    init_kernel<<<(N + 255) / 256, 256>>>(N);
    degree_kernel<<<((E + 3) / 4 + 255) / 256, 256>>>(dst, E);
    wsplit_kernel<<<(FIN * DOUT + 255) / 256, 256>>>(W);
    gemm_kernel<<<(N + 127) / 128, 256>>>(features, N);
    scan1_kernel<<<NB, 256>>>(N);
    scan2_kernel<<<1, 128>>>(NB);
    scan3_kernel<<<(N + 255) / 256, 256>>>(N);
    fill_kernel<<<(E + 255) / 256, 256>>>(src, dst, E);

    long long agg_threads = (long long)N * 32;
    aggregate_kernel<<<(int)((agg_threads + 255) / 256), 256>>>(b, N);

    gather_kernel<<<(NX * 16 + 255) / 256, 256>>>(x, out, NX);
}

// round 5
// speedup vs baseline: 1.7779x; 1.1309x over previous
#include <cuda_runtime.h>
#include <cuda_bf16.h>
#include <cuda_fp16.h>
#include <cstddef>

#define NMAX   100000
#define EMAX   3200000
#define DOUT   64
#define FIN    256
#define NBMAX  128

// Scratch (__device__ globals: allocation-free rule)
__device__ float  g_xw [NMAX * DOUT];         // fp32 xw (self-loop path)
__device__ __half g_xwh[NMAX * DOUT];         // half(xw * dinv[row])  (messages)
__device__ float  g_out[NMAX * DOUT];
__device__ float  g_dinv[NMAX];
__device__ int    g_ecnt[NMAX];
__device__ int    g_off [NMAX];
__device__ int    g_cur [NMAX];
__device__ int    g_csr [EMAX];
__device__ int    g_bsum[NBMAX];
__device__ int    g_bscan[NBMAX];
__device__ __nv_bfloat16 g_wth[DOUT * FIN];   // W^T hi  [64][256]
__device__ __nv_bfloat16 g_wtl[DOUT * FIN];   // W^T lo

// ---------------------------------------------------------------------------
__device__ __forceinline__ unsigned pack_bf2(float x, float y) {
    __nv_bfloat162 t = __floats2bfloat162_rn(x, y);
    return *reinterpret_cast<unsigned*>(&t);
}

__device__ __forceinline__ void ldsm4(unsigned* r, unsigned addr) {
    asm volatile("ldmatrix.sync.aligned.m8n8.x4.shared.b16 {%0,%1,%2,%3}, [%4];\n"
                 : "=r"(r[0]), "=r"(r[1]), "=r"(r[2]), "=r"(r[3]) : "r"(addr));
}

__device__ __forceinline__ void mma_bf16(float* c, const unsigned* a,
                                         unsigned b0, unsigned b1) {
    asm volatile("mma.sync.aligned.m16n8k16.row.col.f32.bf16.bf16.f32 "
                 "{%0,%1,%2,%3}, {%4,%5,%6,%7}, {%8,%9}, {%0,%1,%2,%3};\n"
                 : "+f"(c[0]), "+f"(c[1]), "+f"(c[2]), "+f"(c[3])
                 : "r"(a[0]), "r"(a[1]), "r"(a[2]), "r"(a[3]), "r"(b0), "r"(b1));
}

// ---------------------------------------------------------------------------
// 1) zero edge counts
// ---------------------------------------------------------------------------
__global__ void init_kernel(int n) {
    int i = blockIdx.x * blockDim.x + threadIdx.x;
    if (i < n) g_ecnt[i] = 0;
}

// ---------------------------------------------------------------------------
// 2) in-degree of dst
// ---------------------------------------------------------------------------
__global__ void degree_kernel(const int* __restrict__ dst, int e) {
    int i = blockIdx.x * blockDim.x + threadIdx.x;
    int i4 = i * 4;
    if (i4 + 3 < e) {
        int4 d = *reinterpret_cast<const int4*>(dst + i4);
        atomicAdd(&g_ecnt[d.x], 1);
        atomicAdd(&g_ecnt[d.y], 1);
        atomicAdd(&g_ecnt[d.z], 1);
        atomicAdd(&g_ecnt[d.w], 1);
    } else if (i4 < e) {
        for (int j = i4; j < e; j++) atomicAdd(&g_ecnt[dst[j]], 1);
    }
}

// ---------------------------------------------------------------------------
// 3) split W into hi/lo bf16, transposed to [n][k]
// ---------------------------------------------------------------------------
__global__ void wsplit_kernel(const float* __restrict__ W) {
    int idx = blockIdx.x * blockDim.x + threadIdx.x;
    if (idx < FIN * DOUT) {
        int k = idx >> 6, n = idx & 63;
        float a = W[idx];
        __nv_bfloat16 h = __float2bfloat16(a);
        float r = a - __bfloat162float(h);
        g_wth[n * FIN + k] = h;
        g_wtl[n * FIN + k] = __float2bfloat16(r);
    }
}

// ---------------------------------------------------------------------------
// 4) scan pass 1 (+ dinv fused)
// ---------------------------------------------------------------------------
__global__ void scan1_kernel(int n) {
    __shared__ int warp_sums[8];
    int blk = blockIdx.x, tid = threadIdx.x;
    int base = blk * 1024 + tid * 4;
    int v[4];
#pragma unroll
    for (int j = 0; j < 4; j++) v[j] = (base + j < n) ? g_ecnt[base + j] : 0;
#pragma unroll
    for (int j = 0; j < 4; j++)
        if (base + j < n) g_dinv[base + j] = rsqrtf((float)(v[j] + 1));
    int tsum = v[0] + v[1] + v[2] + v[3];
    int lane = tid & 31, wid = tid >> 5;
    int x = tsum;
#pragma unroll
    for (int o = 1; o < 32; o <<= 1) {
        int y = __shfl_up_sync(~0u, x, o);
        if (lane >= o) x += y;
    }
    if (lane == 31) warp_sums[wid] = x;
    __syncthreads();
    if (wid == 0) {
        int w = (lane < 8) ? warp_sums[lane] : 0;
#pragma unroll
        for (int o = 1; o < 8; o <<= 1) {
            int y = __shfl_up_sync(~0u, w, o);
            if (lane >= o) w += y;
        }
        if (lane < 8) warp_sums[lane] = w;
    }
    __syncthreads();
    int excl = x - tsum + (wid > 0 ? warp_sums[wid - 1] : 0);
    int run = excl;
#pragma unroll
    for (int j = 0; j < 4; j++) {
        if (base + j < n) g_off[base + j] = run;
        run += v[j];
    }
    if (tid == 0) g_bsum[blk] = warp_sums[7];
}

__global__ void scan2_kernel(int nb) {
    __shared__ int ws[4];
    int tid = threadIdx.x, lane = tid & 31, wid = tid >> 5;
    int v = (tid < nb) ? g_bsum[tid] : 0;
    int x = v;
#pragma unroll
    for (int o = 1; o < 32; o <<= 1) {
        int y = __shfl_up_sync(~0u, x, o);
        if (lane >= o) x += y;
    }
    if (lane == 31) ws[wid] = x;
    __syncthreads();
    if (tid == 0) {
        int s = 0;
        for (int i = 0; i < 4; i++) { int t = ws[i]; ws[i] = s; s += t; }
    }
    __syncthreads();
    if (tid < NBMAX) g_bscan[tid] = x - v + ws[wid];
}

__global__ void scan3_kernel(int n) {
    int i = blockIdx.x * blockDim.x + threadIdx.x;
    if (i < n) {
        int o = g_off[i] + g_bscan[i >> 10];
        g_off[i] = o;
        g_cur[i] = o;
    }
}

// ---------------------------------------------------------------------------
// 5) fill CSR
// ---------------------------------------------------------------------------
__global__ void fill_kernel(const int* __restrict__ src,
                            const int* __restrict__ dst, int e) {
    int i = blockIdx.x * blockDim.x + threadIdx.x;
    if (i < e) {
        int d = dst[i];
        int pos = atomicAdd(&g_cur[d], 1);
        g_csr[pos] = src[i];
    }
}

// ---------------------------------------------------------------------------
// 6) GEMM via split-bf16 HMMA, A fragments built directly from gmem.
//    block: 128 rows x 64 cols, 8 warps; warp = 16 rows x 64 cols.
//    W staged in smem in two 128-K chunks; no A smem, no per-step syncs.
// ---------------------------------------------------------------------------
__global__ void __launch_bounds__(256, 2) gemm_kernel(const float* __restrict__ A, int M) {
    __shared__ __align__(16) __nv_bfloat16 Wh[64 * 136];  // [n][128k pad 136]
    __shared__ __align__(16) __nv_bfloat16 Wl[64 * 136];

    const int tid  = threadIdx.x;
    const int lane = tid & 31;
    const int wid  = tid >> 5;
    const int bm   = blockIdx.x * 128;

    const int  r0 = bm + wid * 16 + (lane >> 2);
    const int  r1 = r0 + 8;
    const bool v0 = r0 < M;
    const bool v1 = r1 < M;
    const int  c0 = (lane & 3) * 2;

    const float* pA0 = A + (size_t)r0 * FIN + c0;
    const float* pA1 = A + (size_t)r1 * FIN + c0;

    const unsigned wh_base = (unsigned)__cvta_generic_to_shared(Wh);
    const unsigned wl_base = (unsigned)__cvta_generic_to_shared(Wl);
    const int n_off = (lane & 7) + ((lane >> 4) & 1) * 8;
    const int k_off = ((lane >> 3) & 1) * 8;

    float acc[8][4];
#pragma unroll
    for (int t = 0; t < 8; t++)
#pragma unroll
        for (int j = 0; j < 4; j++) acc[t][j] = 0.f;

    const float2 Z = make_float2(0.f, 0.f);
    float2 cur[4], nxt[4];
    cur[0] = v0 ? *reinterpret_cast<const float2*>(pA0)     : Z;
    cur[1] = v1 ? *reinterpret_cast<const float2*>(pA1)     : Z;
    cur[2] = v0 ? *reinterpret_cast<const float2*>(pA0 + 8) : Z;
    cur[3] = v1 ? *reinterpret_cast<const float2*>(pA1 + 8) : Z;

    for (int kc = 0; kc < 2; kc++) {
        __syncthreads();   // previous chunk's ldsm done before overwrite
        for (int i = tid; i < 1024; i += 256) {
            int row = i >> 4, seg = i & 15;
            *reinterpret_cast<uint4*>(Wh + row * 136 + seg * 8) =
                *reinterpret_cast<const uint4*>(g_wth + row * 256 + kc * 128 + seg * 8);
            *reinterpret_cast<uint4*>(Wl + row * 136 + seg * 8) =
                *reinterpret_cast<const uint4*>(g_wtl + row * 256 + kc * 128 + seg * 8);
        }
        __syncthreads();

#pragma unroll
        for (int k16 = 0; k16 < 8; k16++) {
            // prefetch next k-step's A (cross-chunk too; gmem only)
            int kn = kc * 128 + k16 * 16 + 16;
            if (kn < FIN) {
                nxt[0] = v0 ? *reinterpret_cast<const float2*>(pA0 + kn)     : Z;
                nxt[1] = v1 ? *reinterpret_cast<const float2*>(pA1 + kn)     : Z;
                nxt[2] = v0 ? *reinterpret_cast<const float2*>(pA0 + kn + 8) : Z;
                nxt[3] = v1 ? *reinterpret_cast<const float2*>(pA1 + kn + 8) : Z;
            }

            // build A fragments: hi + residual-lo
            unsigned ah[4], al[4];
#pragma unroll
            for (int j = 0; j < 4; j++) {
                float x = cur[j].x, y = cur[j].y;
                __nv_bfloat16 hx = __float2bfloat16(x);
                __nv_bfloat16 hy = __float2bfloat16(y);
                __nv_bfloat162 hp; hp.x = hx; hp.y = hy;
                ah[j] = *reinterpret_cast<unsigned*>(&hp);
                al[j] = pack_bf2(x - __bfloat162float(hx), y - __bfloat162float(hy));
            }

#pragma unroll
            for (int p = 0; p < 4; p++) {
                unsigned boff = (unsigned)(((p * 16 + n_off) * 136 + k16 * 16 + k_off) * 2);
                unsigned bh[4], bl[4];
                ldsm4(bh, wh_base + boff);
                ldsm4(bl, wl_base + boff);
                mma_bf16(acc[2 * p],     ah, bh[0], bh[1]);
                mma_bf16(acc[2 * p],     al, bh[0], bh[1]);
                mma_bf16(acc[2 * p],     ah, bl[0], bl[1]);
                mma_bf16(acc[2 * p + 1], ah, bh[2], bh[3]);
                mma_bf16(acc[2 * p + 1], al, bh[2], bh[3]);
                mma_bf16(acc[2 * p + 1], ah, bl[2], bl[3]);
            }
#pragma unroll
            for (int j = 0; j < 4; j++) cur[j] = nxt[j];
        }
    }

    // epilogue: fp32 xw + half(xw * dinv[row]) messages
    float dv0 = v0 ? g_dinv[r0] : 0.f;
    float dv1 = v1 ? g_dinv[r1] : 0.f;
#pragma unroll
    for (int nt = 0; nt < 8; nt++) {
        int col = nt * 8 + c0;
        if (v0) {
            float2 w = make_float2(acc[nt][0], acc[nt][1]);
            *reinterpret_cast<float2*>(g_xw + (size_t)r0 * DOUT + col) = w;
            __half2 h = __float22half2_rn(make_float2(w.x * dv0, w.y * dv0));
            *reinterpret_cast<__half2*>(g_xwh + (size_t)r0 * DOUT + col) = h;
        }
        if (v1) {
            float2 w = make_float2(acc[nt][2], acc[nt][3]);
            *reinterpret_cast<float2*>(g_xw + (size_t)r1 * DOUT + col) = w;
            __half2 h = __float22half2_rn(make_float2(w.x * dv1, w.y * dv1));
            *reinterpret_cast<__half2*>(g_xwh + (size_t)r1 * DOUT + col) = h;
        }
    }
}

// ---------------------------------------------------------------------------
// 7) aggregate: one warp per node, fp16 messages, fp32 accumulate
//    out[n] = dinv[n] * sum_in xwh[s] + xw[n]*dinv[n]^2 + b
// ---------------------------------------------------------------------------
__global__ void __launch_bounds__(256) aggregate_kernel(const float* __restrict__ b,
                                                        int n) {
    int node = (blockIdx.x * blockDim.x + threadIdx.x) >> 5;
    int lane = threadIdx.x & 31;
    if (node >= n) return;

    float dn    = g_dinv[node];
    int   start = g_off[node];
    int   end   = start + g_ecnt[node];

    float2 w = *reinterpret_cast<const float2*>(g_xw + ((size_t)node << 6) + (lane << 1));
    float2 sum = make_float2(0.f, 0.f);

    int j = start;
    for (; j + 3 < end; j += 4) {
        int s0 = g_csr[j], s1 = g_csr[j + 1], s2 = g_csr[j + 2], s3 = g_csr[j + 3];
        __half2 h0 = *reinterpret_cast<const __half2*>(g_xwh + ((size_t)s0 << 6) + (lane << 1));
        __half2 h1 = *reinterpret_cast<const __half2*>(g_xwh + ((size_t)s1 << 6) + (lane << 1));
        __half2 h2 = *reinterpret_cast<const __half2*>(g_xwh + ((size_t)s2 << 6) + (lane << 1));
        __half2 h3 = *reinterpret_cast<const __half2*>(g_xwh + ((size_t)s3 << 6) + (lane << 1));
        float2 f0 = __half22float2(h0), f1 = __half22float2(h1);
        float2 f2 = __half22float2(h2), f3 = __half22float2(h3);
        sum.x += f0.x + f1.x + f2.x + f3.x;
        sum.y += f0.y + f1.y + f2.y + f3.y;
    }
    for (; j < end; j++) {
        int s = g_csr[j];
        __half2 h = *reinterpret_cast<const __half2*>(g_xwh + ((size_t)s << 6) + (lane << 1));
        float2 f = __half22float2(h);
        sum.x += f.x; sum.y += f.y;
    }

    float  sl = dn * dn;
    float2 bb = *reinterpret_cast<const float2*>(b + (lane << 1));
    float2 r  = make_float2(w.x * sl + dn * sum.x + bb.x,
                            w.y * sl + dn * sum.y + bb.y);
    *reinterpret_cast<float2*>(g_out + ((size_t)node << 6) + (lane << 1)) = r;
}

// ---------------------------------------------------------------------------
// 8) final gather
// ---------------------------------------------------------------------------
__global__ void gather_kernel(const int* __restrict__ x,
                              float* __restrict__ out, int nidx) {
    int idx = blockIdx.x * blockDim.x + threadIdx.x;
    int i = idx >> 4;
    int q = idx & 15;
    if (i >= nidx) return;
    int nd = x[i];
    float4 v = *reinterpret_cast<const float4*>(g_out + ((size_t)nd << 6) + (q << 2));
    *reinterpret_cast<float4*>(out + ((size_t)i << 6) + (q << 2)) = v;
}

// ---------------------------------------------------------------------------
extern "C" void kernel_launch(void* const* d_in, const int* in_sizes, int n_in,
                              void* d_out, int out_size) {
    const float* features   = (const float*)d_in[0];
    const int*   edge_index = (const int*)  d_in[1];
    const float* W          = (const float*)d_in[2];
    const float* b          = (const float*)d_in[3];
    const int*   x          = (const int*)  d_in[4];
    float*       out        = (float*)d_out;

    const int N  = in_sizes[0] / FIN;
    const int E  = in_sizes[1] / 2;
    const int NX = in_sizes[4];

    const int* src = edge_index;
    const int* dst = edge_index + E;
    const int NB = (N + 1023) / 1024;

    init_kernel<<<(N + 255) / 256, 256>>>(N);
    degree_kernel<<<((E + 3) / 4 + 255) / 256, 256>>>(dst, E);
    wsplit_kernel<<<(FIN * DOUT + 255) / 256, 256>>>(W);
    scan1_kernel<<<NB, 256>>>(N);          // computes g_dinv too (needed by gemm)
    scan2_kernel<<<1, 128>>>(NB);
    scan3_kernel<<<(N + 255) / 256, 256>>>(N);
    gemm_kernel<<<(N + 127) / 128, 256>>>(features, N);
    fill_kernel<<<(E + 255) / 256, 256>>>(src, dst, E);

    long long agg_threads = (long long)N * 32;
    aggregate_kernel<<<(int)((agg_threads + 255) / 256), 256>>>(b, N);

    gather_kernel<<<(NX * 16 + 255) / 256, 256>>>(x, out, NX);
}

// round 7
// speedup vs baseline: 1.8583x; 1.0452x over previous
#include <cuda_runtime.h>
#include <cuda_bf16.h>
#include <cuda_fp16.h>
#include <cstddef>

#define NMAX   100000
#define EMAX   3200000
#define DOUT   64
#define FIN    256
#define NBMAX  128

// Scratch (__device__ globals: allocation-free rule)
__device__ float  g_xw [NMAX * DOUT];         // fp32 xw (self-loop path)
__device__ __half g_xwh[NMAX * DOUT];         // half(xw * dinv[row])  (messages)
__device__ float  g_out[NMAX * DOUT];
__device__ float  g_dinv[NMAX];
__device__ int    g_ecnt[NMAX];
__device__ int    g_off [NMAX];
__device__ int    g_cur [NMAX];
__device__ int    g_csr [EMAX];
__device__ int    g_bsum[NBMAX];
__device__ int    g_bscan[NBMAX];
__device__ __nv_bfloat16 g_wth[DOUT * FIN];   // W^T hi  [64][256]
__device__ __nv_bfloat16 g_wtl[DOUT * FIN];   // W^T lo

// ---------------------------------------------------------------------------
__device__ __forceinline__ unsigned pack_bf2(float x, float y) {
    __nv_bfloat162 t = __floats2bfloat162_rn(x, y);
    return *reinterpret_cast<unsigned*>(&t);
}

__device__ __forceinline__ void ldsm4(unsigned* r, unsigned addr) {
    asm volatile("ldmatrix.sync.aligned.m8n8.x4.shared.b16 {%0,%1,%2,%3}, [%4];\n"
                 : "=r"(r[0]), "=r"(r[1]), "=r"(r[2]), "=r"(r[3]) : "r"(addr));
}

__device__ __forceinline__ void mma_bf16(float* c, const unsigned* a,
                                         unsigned b0, unsigned b1) {
    asm volatile("mma.sync.aligned.m16n8k16.row.col.f32.bf16.bf16.f32 "
                 "{%0,%1,%2,%3}, {%4,%5,%6,%7}, {%8,%9}, {%0,%1,%2,%3};\n"
                 : "+f"(c[0]), "+f"(c[1]), "+f"(c[2]), "+f"(c[3])
                 : "r"(a[0]), "r"(a[1]), "r"(a[2]), "r"(a[3]), "r"(b0), "r"(b1));
}

// ---------------------------------------------------------------------------
// 1) zero edge counts
// ---------------------------------------------------------------------------
__global__ void init_kernel(int n) {
    int i = blockIdx.x * blockDim.x + threadIdx.x;
    if (i < n) g_ecnt[i] = 0;
}

// ---------------------------------------------------------------------------
// 2) in-degree of dst
// ---------------------------------------------------------------------------
__global__ void degree_kernel(const int* __restrict__ dst, int e) {
    int i = blockIdx.x * blockDim.x + threadIdx.x;
    int i4 = i * 4;
    if (i4 + 3 < e) {
        int4 d = *reinterpret_cast<const int4*>(dst + i4);
        atomicAdd(&g_ecnt[d.x], 1);
        atomicAdd(&g_ecnt[d.y], 1);
        atomicAdd(&g_ecnt[d.z], 1);
        atomicAdd(&g_ecnt[d.w], 1);
    } else if (i4 < e) {
        for (int j = i4; j < e; j++) atomicAdd(&g_ecnt[dst[j]], 1);
    }
}

// ---------------------------------------------------------------------------
// 3) split W into hi/lo bf16, transposed to [n][k]
// ---------------------------------------------------------------------------
__global__ void wsplit_kernel(const float* __restrict__ W) {
    int idx = blockIdx.x * blockDim.x + threadIdx.x;
    if (idx < FIN * DOUT) {
        int k = idx >> 6, n = idx & 63;
        float a = W[idx];
        __nv_bfloat16 h = __float2bfloat16(a);
        float r = a - __bfloat162float(h);
        g_wth[n * FIN + k] = h;
        g_wtl[n * FIN + k] = __float2bfloat16(r);
    }
}

// ---------------------------------------------------------------------------
// 4) scan pass 1 (+ dinv fused)
// ---------------------------------------------------------------------------
__global__ void scan1_kernel(int n) {
    __shared__ int warp_sums[8];
    int blk = blockIdx.x, tid = threadIdx.x;
    int base = blk * 1024 + tid * 4;
    int v[4];
#pragma unroll
    for (int j = 0; j < 4; j++) v[j] = (base + j < n) ? g_ecnt[base + j] : 0;
#pragma unroll
    for (int j = 0; j < 4; j++)
        if (base + j < n) g_dinv[base + j] = rsqrtf((float)(v[j] + 1));
    int tsum = v[0] + v[1] + v[2] + v[3];
    int lane = tid & 31, wid = tid >> 5;
    int x = tsum;
#pragma unroll
    for (int o = 1; o < 32; o <<= 1) {
        int y = __shfl_up_sync(~0u, x, o);
        if (lane >= o) x += y;
    }
    if (lane == 31) warp_sums[wid] = x;
    __syncthreads();
    if (wid == 0) {
        int w = (lane < 8) ? warp_sums[lane] : 0;
#pragma unroll
        for (int o = 1; o < 8; o <<= 1) {
            int y = __shfl_up_sync(~0u, w, o);
            if (lane >= o) w += y;
        }
        if (lane < 8) warp_sums[lane] = w;
    }
    __syncthreads();
    int excl = x - tsum + (wid > 0 ? warp_sums[wid - 1] : 0);
    int run = excl;
#pragma unroll
    for (int j = 0; j < 4; j++) {
        if (base + j < n) g_off[base + j] = run;
        run += v[j];
    }
    if (tid == 0) g_bsum[blk] = warp_sums[7];
}

__global__ void scan2_kernel(int nb) {
    __shared__ int ws[4];
    int tid = threadIdx.x, lane = tid & 31, wid = tid >> 5;
    int v = (tid < nb) ? g_bsum[tid] : 0;
    int x = v;
#pragma unroll
    for (int o = 1; o < 32; o <<= 1) {
        int y = __shfl_up_sync(~0u, x, o);
        if (lane >= o) x += y;
    }
    if (lane == 31) ws[wid] = x;
    __syncthreads();
    if (tid == 0) {
        int s = 0;
        for (int i = 0; i < 4; i++) { int t = ws[i]; ws[i] = s; s += t; }
    }
    __syncthreads();
    if (tid < NBMAX) g_bscan[tid] = x - v + ws[wid];
}

__global__ void scan3_kernel(int n) {
    int i = blockIdx.x * blockDim.x + threadIdx.x;
    if (i < n) {
        int o = g_off[i] + g_bscan[i >> 10];
        g_off[i] = o;
        g_cur[i] = o;
    }
}

// ---------------------------------------------------------------------------
// 5) fused GEMM + CSR-fill.  Every 5th block is a GEMM block (bm from bx/5);
//    the other 4/5 are fill blocks (4 edges/thread).  Interleaved roles keep
//    both kinds co-resident across waves -> atomics overlap tensor work.
// ---------------------------------------------------------------------------
__global__ void __launch_bounds__(256, 2) gemm_fill_kernel(
        const float* __restrict__ A, int M,
        const int* __restrict__ src, const int* __restrict__ dst, int e) {
    __shared__ __align__(16) __nv_bfloat16 Wh[64 * 136];  // [n][128k pad 136]
    __shared__ __align__(16) __nv_bfloat16 Wl[64 * 136];

    const int bx = blockIdx.x;

    if ((bx % 5) != 0) {
        // ---- fill role ----
        int fb = (bx / 5) * 4 + (bx % 5) - 1;          // 0..(4*nGemm-1)
        int i4 = (fb * 256 + threadIdx.x) * 4;
        if (i4 + 3 < e) {
            int4 d = *reinterpret_cast<const int4*>(dst + i4);
            int4 s = *reinterpret_cast<const int4*>(src + i4);
            int p0 = atomicAdd(&g_cur[d.x], 1);
            int p1 = atomicAdd(&g_cur[d.y], 1);
            int p2 = atomicAdd(&g_cur[d.z], 1);
            int p3 = atomicAdd(&g_cur[d.w], 1);
            g_csr[p0] = s.x;
            g_csr[p1] = s.y;
            g_csr[p2] = s.z;
            g_csr[p3] = s.w;
        } else if (i4 < e) {
            for (int j = i4; j < e; j++) {
                int d = dst[j];
                int pos = atomicAdd(&g_cur[d], 1);
                g_csr[pos] = src[j];
            }
        }
        return;
    }

    // ---- GEMM role ----
    const int tid  = threadIdx.x;
    const int lane = tid & 31;
    const int wid  = tid >> 5;
    const int bm   = (bx / 5) * 128;

    const int  r0 = bm + wid * 16 + (lane >> 2);
    const int  r1 = r0 + 8;
    const bool v0 = r0 < M;
    const bool v1 = r1 < M;
    const int  c0 = (lane & 3) * 2;

    const float* pA0 = A + (size_t)r0 * FIN + c0;
    const float* pA1 = A + (size_t)r1 * FIN + c0;

    const unsigned wh_base = (unsigned)__cvta_generic_to_shared(Wh);
    const unsigned wl_base = (unsigned)__cvta_generic_to_shared(Wl);
    const int n_off = (lane & 7) + ((lane >> 4) & 1) * 8;
    const int k_off = ((lane >> 3) & 1) * 8;

    float acc[8][4];
#pragma unroll
    for (int t = 0; t < 8; t++)
#pragma unroll
        for (int j = 0; j < 4; j++) acc[t][j] = 0.f;

    const float2 Z = make_float2(0.f, 0.f);
    float2 cur[4], nxt[4];
    cur[0] = v0 ? *reinterpret_cast<const float2*>(pA0)     : Z;
    cur[1] = v1 ? *reinterpret_cast<const float2*>(pA1)     : Z;
    cur[2] = v0 ? *reinterpret_cast<const float2*>(pA0 + 8) : Z;
    cur[3] = v1 ? *reinterpret_cast<const float2*>(pA1 + 8) : Z;

    for (int kc = 0; kc < 2; kc++) {
        __syncthreads();   // previous chunk's ldsm done before overwrite
        for (int i = tid; i < 1024; i += 256) {
            int row = i >> 4, seg = i & 15;
            *reinterpret_cast<uint4*>(Wh + row * 136 + seg * 8) =
                *reinterpret_cast<const uint4*>(g_wth + row * 256 + kc * 128 + seg * 8);
            *reinterpret_cast<uint4*>(Wl + row * 136 + seg * 8) =
                *reinterpret_cast<const uint4*>(g_wtl + row * 256 + kc * 128 + seg * 8);
        }
        __syncthreads();

#pragma unroll
        for (int k16 = 0; k16 < 8; k16++) {
            int kn = kc * 128 + k16 * 16 + 16;
            if (kn < FIN) {
                nxt[0] = v0 ? *reinterpret_cast<const float2*>(pA0 + kn)     : Z;
                nxt[1] = v1 ? *reinterpret_cast<const float2*>(pA1 + kn)     : Z;
                nxt[2] = v0 ? *reinterpret_cast<const float2*>(pA0 + kn + 8) : Z;
                nxt[3] = v1 ? *reinterpret_cast<const float2*>(pA1 + kn + 8) : Z;
            }

            unsigned ah[4], al[4];
#pragma unroll
            for (int j = 0; j < 4; j++) {
                float x = cur[j].x, y = cur[j].y;
                __nv_bfloat16 hx = __float2bfloat16(x);
                __nv_bfloat16 hy = __float2bfloat16(y);
                __nv_bfloat162 hp; hp.x = hx; hp.y = hy;
                ah[j] = *reinterpret_cast<unsigned*>(&hp);
                al[j] = pack_bf2(x - __bfloat162float(hx), y - __bfloat162float(hy));
            }

#pragma unroll
            for (int p = 0; p < 4; p++) {
                unsigned boff = (unsigned)(((p * 16 + n_off) * 136 + k16 * 16 + k_off) * 2);
                unsigned bh[4], bl[4];
                ldsm4(bh, wh_base + boff);
                ldsm4(bl, wl_base + boff);
                mma_bf16(acc[2 * p],     ah, bh[0], bh[1]);
                mma_bf16(acc[2 * p],     al, bh[0], bh[1]);
                mma_bf16(acc[2 * p],     ah, bl[0], bl[1]);
                mma_bf16(acc[2 * p + 1], ah, bh[2], bh[3]);
                mma_bf16(acc[2 * p + 1], al, bh[2], bh[3]);
                mma_bf16(acc[2 * p + 1], ah, bl[2], bl[3]);
            }
#pragma unroll
            for (int j = 0; j < 4; j++) cur[j] = nxt[j];
        }
    }

    // epilogue: fp32 xw + half(xw * dinv[row]) messages
    float dv0 = v0 ? g_dinv[r0] : 0.f;
    float dv1 = v1 ? g_dinv[r1] : 0.f;
#pragma unroll
    for (int nt = 0; nt < 8; nt++) {
        int col = nt * 8 + c0;
        if (v0) {
            float2 w = make_float2(acc[nt][0], acc[nt][1]);
            *reinterpret_cast<float2*>(g_xw + (size_t)r0 * DOUT + col) = w;
            __half2 h = __float22half2_rn(make_float2(w.x * dv0, w.y * dv0));
            *reinterpret_cast<__half2*>(g_xwh + (size_t)r0 * DOUT + col) = h;
        }
        if (v1) {
            float2 w = make_float2(acc[nt][2], acc[nt][3]);
            *reinterpret_cast<float2*>(g_xw + (size_t)r1 * DOUT + col) = w;
            __half2 h = __float22half2_rn(make_float2(w.x * dv1, w.y * dv1));
            *reinterpret_cast<__half2*>(g_xwh + (size_t)r1 * DOUT + col) = h;
        }
    }
}

// ---------------------------------------------------------------------------
// 6) aggregate: one warp per node, fp16 messages, fp32 accumulate
// ---------------------------------------------------------------------------
__global__ void __launch_bounds__(256) aggregate_kernel(const float* __restrict__ b,
                                                        int n) {
    int node = (blockIdx.x * blockDim.x + threadIdx.x) >> 5;
    int lane = threadIdx.x & 31;
    if (node >= n) return;

    float dn    = g_dinv[node];
    int   start = g_off[node];
    int   end   = start + g_ecnt[node];

    float2 w = *reinterpret_cast<const float2*>(g_xw + ((size_t)node << 6) + (lane << 1));
    float2 sum = make_float2(0.f, 0.f);

    int j = start;
    for (; j + 3 < end; j += 4) {
        int s0 = g_csr[j], s1 = g_csr[j + 1], s2 = g_csr[j + 2], s3 = g_csr[j + 3];
        __half2 h0 = *reinterpret_cast<const __half2*>(g_xwh + ((size_t)s0 << 6) + (lane << 1));
        __half2 h1 = *reinterpret_cast<const __half2*>(g_xwh + ((size_t)s1 << 6) + (lane << 1));
        __half2 h2 = *reinterpret_cast<const __half2*>(g_xwh + ((size_t)s2 << 6) + (lane << 1));
        __half2 h3 = *reinterpret_cast<const __half2*>(g_xwh + ((size_t)s3 << 6) + (lane << 1));
        float2 f0 = __half22float2(h0), f1 = __half22float2(h1);
        float2 f2 = __half22float2(h2), f3 = __half22float2(h3);
        sum.x += f0.x + f1.x + f2.x + f3.x;
        sum.y += f0.y + f1.y + f2.y + f3.y;
    }
    for (; j < end; j++) {
        int s = g_csr[j];
        __half2 h = *reinterpret_cast<const __half2*>(g_xwh + ((size_t)s << 6) + (lane << 1));
        float2 f = __half22float2(h);
        sum.x += f.x; sum.y += f.y;
    }

    float  sl = dn * dn;
    float2 bb = *reinterpret_cast<const float2*>(b + (lane << 1));
    float2 r  = make_float2(w.x * sl + dn * sum.x + bb.x,
                            w.y * sl + dn * sum.y + bb.y);
    *reinterpret_cast<float2*>(g_out + ((size_t)node << 6) + (lane << 1)) = r;
}

// ---------------------------------------------------------------------------
// 7) final gather
// ---------------------------------------------------------------------------
__global__ void gather_kernel(const int* __restrict__ x,
                              float* __restrict__ out, int nidx) {
    int idx = blockIdx.x * blockDim.x + threadIdx.x;
    int i = idx >> 4;
    int q = idx & 15;
    if (i >= nidx) return;
    int nd = x[i];
    float4 v = *reinterpret_cast<const float4*>(g_out + ((size_t)nd << 6) + (q << 2));
    *reinterpret_cast<float4*>(out + ((size_t)i << 6) + (q << 2)) = v;
}

// ---------------------------------------------------------------------------
extern "C" void kernel_launch(void* const* d_in, const int* in_sizes, int n_in,
                              void* d_out, int out_size) {
    const float* features   = (const float*)d_in[0];
    const int*   edge_index = (const int*)  d_in[1];
    const float* W          = (const float*)d_in[2];
    const float* b          = (const float*)d_in[3];
    const int*   x          = (const int*)  d_in[4];
    float*       out        = (float*)d_out;

    const int N  = in_sizes[0] / FIN;
    const int E  = in_sizes[1] / 2;
    const int NX = in_sizes[4];

    const int* src = edge_index;
    const int* dst = edge_index + E;
    const int NB = (N + 1023) / 1024;

    init_kernel<<<(N + 255) / 256, 256>>>(N);
    degree_kernel<<<((E + 3) / 4 + 255) / 256, 256>>>(dst, E);
    wsplit_kernel<<<(FIN * DOUT + 255) / 256, 256>>>(W);
    scan1_kernel<<<NB, 256>>>(N);          // also computes g_dinv (gemm needs it)
    scan2_kernel<<<1, 128>>>(NB);
    scan3_kernel<<<(N + 255) / 256, 256>>>(N);

    // fused GEMM + CSR fill.  nGemm blocks must also provide enough fill
    // blocks: 4*nGemm*1024 edges >= E.  nGemm=782 -> 3.2M capacity = OK.
    int nGemm = (N + 127) / 128;
    int nFillNeeded = (E + 1023) / 1024;
    if (nGemm * 4 < nFillNeeded) nGemm = (nFillNeeded + 3) / 4;  // safety
    gemm_fill_kernel<<<nGemm * 5, 256>>>(features, N, src, dst, E);

    long long agg_threads = (long long)N * 32;
    aggregate_kernel<<<(int)((agg_threads + 255) / 256), 256>>>(b, N);

    gather_kernel<<<(NX * 16 + 255) / 256, 256>>>(x, out, NX);
}